// round 11
// baseline (speedup 1.0000x reference)
#include <cuda_runtime.h>

#define T_STEPS 4096
#define RES     2048
#define NF      8
#define NO      8
#define GRID_B  128
#define BLOCK_B 256
#define NC      16            // output columns per CTA
#define SENT    0xFFC00000u   // NaN bit pattern — finite math never makes it

// Scratch (allocation-free rule: device globals)
__device__ float g_drive[T_STEPS * RES];   // 32 MB
__device__ float g_X[T_STEPS * RES];       // 32 MB, sentinel-poisoned each run

__device__ __forceinline__ unsigned long long ffma2(unsigned long long a,
                                                    unsigned long long b,
                                                    unsigned long long c) {
    unsigned long long d;
    asm("fma.rn.f32x2 %0, %1, %2, %3;" : "=l"(d) : "l"(a), "l"(b), "l"(c));
    return d;
}
__device__ __forceinline__ unsigned long long pack2(float x, float y) {
    unsigned long long d;
    asm("mov.b64 %0, {%1, %2};" : "=l"(d) : "f"(x), "f"(y));
    return d;
}
__device__ __forceinline__ uint4 ldv_u4(const uint4* p) {
    uint4 v;
    asm volatile("ld.volatile.global.v4.u32 {%0,%1,%2,%3}, [%4];"
                 : "=r"(v.x), "=r"(v.y), "=r"(v.z), "=r"(v.w) : "l"(p));
    return v;
}
__device__ __forceinline__ bool okq(const uint4& v) {
    return (v.x != SENT) & (v.y != SENT) & (v.z != SENT) & (v.w != SENT);
}
// fast tanh: (e^{2x}-1)/(e^{2x}+1); args bounded far below overflow
__device__ __forceinline__ float ftanh(float x) {
    float e = __expf(2.0f * x);
    return __fdividef(e - 1.0f, e + 1.0f);
}

// ---------------------------------------------------------------------------
// Kernel A: drive[t][r] = win_bias[r] + inp[t] @ win_u[:, r]
//           + poison g_X[t][r] with the sentinel (re-done every run)
// ---------------------------------------------------------------------------
__global__ void drive_kernel(const float* __restrict__ inp,
                             const float* __restrict__ Win) {
    int t = blockIdx.y;
    int r = blockIdx.x * blockDim.x + threadIdx.x;
    reinterpret_cast<unsigned int*>(g_X)[(size_t)t * RES + r] = SENT;
    float acc = Win[r];                       // bias row (Win[0])
#pragma unroll
    for (int f = 0; f < NF; f++)
        acc += inp[t * NF + f] * Win[(1 + f) * RES + r];
    g_drive[t * RES + r] = acc;
}

// ---------------------------------------------------------------------------
// Kernel B: persistent scan — fully barrier-free steady state.
//   Matvec warps: FMA partial -> volatile sred write -> straight into
//   half-warp poll of own 128-float g_X[t] sub-slice (8 producers).
//   Warp 0 additionally: volatile-LDS spin on the 8 sred slots (parity
//   double-buffered, SENT sentinel, reset-after-read), sum, ftanh, publish.
// ---------------------------------------------------------------------------
__global__ void __launch_bounds__(BLOCK_B, 1)
scan_kernel(const float* __restrict__ W) {
    __shared__ float sx[RES];                     // x_t; warp-private slices
    __shared__ unsigned int sred[2][8][NC];       // partial bits, parity-buffered

    const int tid  = threadIdx.x;
    const int w    = tid >> 5;
    const int lane = tid & 31;
    const int col  = lane & 15;
    const int half = lane >> 4;
    const int hl   = lane & 15;                   // lane within half
    const unsigned hmask = half ? 0xFFFF0000u : 0x0000FFFFu;
    const int cb   = blockIdx.x;
    const int cbj  = cb * NC;                     // column base of this CTA
    const int jg   = cbj + col;                   // global output column
    const int i0   = w * 256 + half * 128;        // this lane's 128-row chunk

    const float dmp = 0.3f;
    const float omd = 1.0f - 0.3f;

    // --- one-time: W slice (128 rows x 1 col) into registers
    unsigned long long wrA[32], wrB[32];
#pragma unroll
    for (int k = 0; k < 32; k++) {
        int i = i0 + 4 * k;
        wrA[k] = pack2(__ldg(&W[(size_t)i * RES + jg]),
                       __ldg(&W[(size_t)(i + 1) * RES + jg]));
        wrB[k] = pack2(__ldg(&W[(size_t)(i + 2) * RES + jg]),
                       __ldg(&W[(size_t)(i + 3) * RES + jg]));
    }

    // init: x_0 = 0 (own slice), own sred slots = SENT
    float4* sx4 = reinterpret_cast<float4*>(sx);
    sx4[w * 64 + lane]      = make_float4(0.f, 0.f, 0.f, 0.f);
    sx4[w * 64 + 32 + lane] = make_float4(0.f, 0.f, 0.f, 0.f);
    if (half == 0) {
        sred[0][w][col] = SENT;
        sred[1][w][col] = SENT;
    }
    __syncthreads();   // startup only — no barriers after this

    const ulonglong2* sxu2 =
        reinterpret_cast<const ulonglong2*>(sx) + (w * 64 + half * 32);
    const int qbase = i0 >> 2;            // uint4 index of own half sub-slice

    float xold = 0.0f;   // warp 0 lanes 0-15: running x for own column
    float drv  = 0.0f;   // warp 0 lanes 0-15: prefetched drive
    if (w == 0 && lane < NC) drv = __ldcg(&g_drive[cbj + lane]);

    for (int t = 0; t < T_STEPS; t++) {
        // ---- matvec partial: 32 broadcast LDS.128 + 64 fma.f32x2, 4 chains
        unsigned long long a0 = 0ull, a1 = 0ull, a2 = 0ull, a3 = 0ull;
#pragma unroll
        for (int k = 0; k < 32; k += 2) {
            ulonglong2 x0 = sxu2[k];
            ulonglong2 x1 = sxu2[k + 1];
            a0 = ffma2(wrA[k],     x0.x, a0);
            a1 = ffma2(wrB[k],     x0.y, a1);
            a2 = ffma2(wrA[k + 1], x1.x, a2);
            a3 = ffma2(wrB[k + 1], x1.y, a3);
        }
        float2 f0 = *reinterpret_cast<float2*>(&a0);
        float2 f1 = *reinterpret_cast<float2*>(&a1);
        float2 f2 = *reinterpret_cast<float2*>(&a2);
        float2 f3 = *reinterpret_cast<float2*>(&a3);
        float s = ((f0.x + f0.y) + (f1.x + f1.y)) +
                  ((f2.x + f2.y) + (f3.x + f3.y));
        s += __shfl_down_sync(0xffffffffu, s, 16);     // fold halves (join)
        if (half == 0)
            *((volatile unsigned int*)&sred[t & 1][w][col]) = __float_as_uint(s);

        const bool more = (t < T_STEPS - 1);

        // ---- pre-issue first poll sample (flies during finalize/others' work)
        const uint4* p =
            reinterpret_cast<const uint4*>(&g_X[(size_t)t * RES]) + qbase;
        uint4 A0, A1;
        if (more) { A0 = ldv_u4(p + hl); A1 = ldv_u4(p + hl + 16); }

        // ---- warp 0: dataflow finalize (spin on sred, no barrier)
        if (w == 0) {
            const int par = t & 1;
            unsigned u0, u1, u2, u3, u4, u5, u6, u7;
            for (;;) {
                bool ok = true;
                if (lane < NC) {
                    volatile unsigned int* sp = &sred[par][0][lane];
                    u0 = sp[0 * NC]; u1 = sp[1 * NC];
                    u2 = sp[2 * NC]; u3 = sp[3 * NC];
                    u4 = sp[4 * NC]; u5 = sp[5 * NC];
                    u6 = sp[6 * NC]; u7 = sp[7 * NC];
                    ok = (u0 != SENT) & (u1 != SENT) & (u2 != SENT) &
                         (u3 != SENT) & (u4 != SENT) & (u5 != SENT) &
                         (u6 != SENT) & (u7 != SENT);
                }
                if (__all_sync(0xffffffffu, ok)) break;
            }
            if (lane < NC) {
                volatile unsigned int* sp = &sred[par][0][lane];
#pragma unroll
                for (int ww = 0; ww < 8; ww++) sp[ww * NC] = SENT;  // reset

                float tot = ((__uint_as_float(u0) + __uint_as_float(u1)) +
                             (__uint_as_float(u2) + __uint_as_float(u3))) +
                            ((__uint_as_float(u4) + __uint_as_float(u5)) +
                             (__uint_as_float(u6) + __uint_as_float(u7)));
                float xn = omd * xold + dmp * ftanh(drv + tot);
                xold = xn;
                __stcg(&g_X[(size_t)t * RES + cbj + lane], xn);    // signal
                if (more)
                    drv = __ldcg(&g_drive[(size_t)(t + 1) * RES + cbj + lane]);
            }
        }
        if (!more) break;

        // ---- half-warp dataflow poll of own 128-float sub-slice of g_X[t]
        for (;;) {
            if (__all_sync(hmask, okq(A0) & okq(A1))) break;
            A0 = ldv_u4(p + hl);
            A1 = ldv_u4(p + hl + 16);
        }
        sx4[qbase + hl]      = *reinterpret_cast<float4*>(&A0);
        sx4[qbase + 16 + hl] = *reinterpret_cast<float4*>(&A1);
        __syncwarp(hmask);
    }
}

// ---------------------------------------------------------------------------
// Kernel C: Y[t] = wout_bias + inp[t] @ wout_u + x_{t+1} @ wout_x
// ---------------------------------------------------------------------------
__global__ void readout_kernel(const float* __restrict__ inp,
                               const float* __restrict__ Wout,
                               float* __restrict__ out) {
    const int w    = threadIdx.x >> 5;
    const int lane = threadIdx.x & 31;
    const int t    = blockIdx.x * 8 + w;

    float acc[NO];
#pragma unroll
    for (int o = 0; o < NO; o++) acc[o] = 0.0f;

    const float* xrow = &g_X[(size_t)t * RES];
    for (int it = 0; it < RES / 32; it++) {
        int r = it * 32 + lane;
        float xv = xrow[r];
        const float4* wrow =
            reinterpret_cast<const float4*>(&Wout[(size_t)(1 + NF + r) * NO]);
        float4 wa = wrow[0], wb = wrow[1];
        acc[0] += xv * wa.x; acc[1] += xv * wa.y;
        acc[2] += xv * wa.z; acc[3] += xv * wa.w;
        acc[4] += xv * wb.x; acc[5] += xv * wb.y;
        acc[6] += xv * wb.z; acc[7] += xv * wb.w;
    }
#pragma unroll
    for (int o = 0; o < NO; o++) {
#pragma unroll
        for (int sft = 16; sft > 0; sft >>= 1)
            acc[o] += __shfl_down_sync(0xffffffffu, acc[o], sft);
    }
    if (lane == 0) {
#pragma unroll
        for (int o = 0; o < NO; o++) {
            float y = Wout[o];
#pragma unroll
            for (int f = 0; f < NF; f++)
                y += inp[t * NF + f] * Wout[(1 + f) * NO + o];
            out[t * NO + o] = y + acc[o];
        }
    }
}

// ---------------------------------------------------------------------------
extern "C" void kernel_launch(void* const* d_in, const int* in_sizes, int n_in,
                              void* d_out, int out_size) {
    const float* inp  = (const float*)d_in[0];   // (4096, 8)
    const float* Win  = (const float*)d_in[1];   // (9, 2048)
    const float* W    = (const float*)d_in[2];   // (2048, 2048)
    const float* Wout = (const float*)d_in[3];   // (2057, 8)
    float* out = (float*)d_out;                  // (4096, 8) fp32

    dim3 ga(RES / 256, T_STEPS);
    drive_kernel<<<ga, 256>>>(inp, Win);         // also poisons g_X
    scan_kernel<<<GRID_B, BLOCK_B>>>(W);
    readout_kernel<<<T_STEPS / 8, 256>>>(inp, Wout, out);
}

// round 12
// speedup vs baseline: 1.2273x; 1.2273x over previous
#include <cuda_runtime.h>

#define T_STEPS 4096
#define RES     2048
#define NF      8
#define NO      8
#define GRID_B  128
#define BLOCK_B 512           // 16 matvec warps
#define NW      16            // warps per CTA
#define NC      16            // output columns per CTA
#define SENT    0xFFC00000u   // NaN bit pattern — finite math never makes it

// Scratch (allocation-free rule: device globals)
__device__ float g_drive[T_STEPS * RES];   // 32 MB
__device__ float g_X[T_STEPS * RES];       // 32 MB, sentinel-poisoned each run

__device__ __forceinline__ unsigned long long ffma2(unsigned long long a,
                                                    unsigned long long b,
                                                    unsigned long long c) {
    unsigned long long d;
    asm("fma.rn.f32x2 %0, %1, %2, %3;" : "=l"(d) : "l"(a), "l"(b), "l"(c));
    return d;
}
__device__ __forceinline__ unsigned long long pack2(float x, float y) {
    unsigned long long d;
    asm("mov.b64 %0, {%1, %2};" : "=l"(d) : "f"(x), "f"(y));
    return d;
}
__device__ __forceinline__ uint4 ldv_u4(const uint4* p) {
    uint4 v;
    asm volatile("ld.volatile.global.v4.u32 {%0,%1,%2,%3}, [%4];"
                 : "=r"(v.x), "=r"(v.y), "=r"(v.z), "=r"(v.w) : "l"(p));
    return v;
}
__device__ __forceinline__ bool okq(const uint4& v) {
    return (v.x != SENT) & (v.y != SENT) & (v.z != SENT) & (v.w != SENT);
}
// fast tanh: (e^{2x}-1)/(e^{2x}+1); args bounded far below overflow
__device__ __forceinline__ float ftanh(float x) {
    float e = __expf(2.0f * x);
    return __fdividef(e - 1.0f, e + 1.0f);
}

// ---------------------------------------------------------------------------
// Kernel A: drive[t][r] = win_bias[r] + inp[t] @ win_u[:, r]
//           + poison g_X[t][r] with the sentinel (re-done every run)
// ---------------------------------------------------------------------------
__global__ void drive_kernel(const float* __restrict__ inp,
                             const float* __restrict__ Win) {
    int t = blockIdx.y;
    int r = blockIdx.x * blockDim.x + threadIdx.x;
    reinterpret_cast<unsigned int*>(g_X)[(size_t)t * RES + r] = SENT;
    float acc = Win[r];                       // bias row (Win[0])
#pragma unroll
    for (int f = 0; f < NF; f++)
        acc += inp[t * NF + f] * Win[(1 + f) * RES + r];
    g_drive[t * RES + r] = acc;
}

// ---------------------------------------------------------------------------
// Kernel B: persistent scan, R9 skeleton (ONE barrier, warp-0 finalize,
// pre-issued single-pump data polls) at 512 threads / 16 warps:
//   warp w owns rows [w*128,(w+1)*128) x 16 cols of W in regs (32 ULLs/lane),
//   matvec = 16 LDS.128 + 32 fma.f32x2 (4 chains), poll = ONE uint4/lane.
// ---------------------------------------------------------------------------
__global__ void __launch_bounds__(BLOCK_B, 1)
scan_kernel(const float* __restrict__ W) {
    __shared__ float sx[RES];              // x_t; warp-private 128-slices
    __shared__ float sred[2][NW][NC];      // partials, parity double-buffered

    const int tid  = threadIdx.x;
    const int w    = tid >> 5;
    const int lane = tid & 31;
    const int col  = lane & 15;
    const int half = lane >> 4;
    const int cb   = blockIdx.x;
    const int cbj  = cb * NC;              // column base of this CTA
    const int jg   = cbj + col;            // global output column
    const int i0   = w * 128 + half * 64;  // this lane's 64-row chunk

    const float dmp = 0.3f;
    const float omd = 1.0f - 0.3f;

    // --- one-time: W slice (64 rows x 1 col) into registers
    unsigned long long wrA[16], wrB[16];
#pragma unroll
    for (int k = 0; k < 16; k++) {
        int i = i0 + 4 * k;
        wrA[k] = pack2(__ldg(&W[(size_t)i * RES + jg]),
                       __ldg(&W[(size_t)(i + 1) * RES + jg]));
        wrB[k] = pack2(__ldg(&W[(size_t)(i + 2) * RES + jg]),
                       __ldg(&W[(size_t)(i + 3) * RES + jg]));
    }

    // x_0 = 0
    float4* sx4 = reinterpret_cast<float4*>(sx);
    sx4[tid] = make_float4(0.f, 0.f, 0.f, 0.f);
    __syncthreads();

    const ulonglong2* sxu2 =
        reinterpret_cast<const ulonglong2*>(sx) + (w * 32 + half * 16);

    float xold = 0.0f;   // warp 0 lanes 0-15: running x for own column
    float drv  = 0.0f;   // warp 0 lanes 0-15: prefetched drive
    if (w == 0 && lane < NC) drv = __ldcg(&g_drive[cbj + lane]);

    for (int t = 0; t < T_STEPS; t++) {
        // ---- matvec partial: 16 broadcast LDS.128 + 32 fma.f32x2, 4 chains
        unsigned long long a0 = 0ull, a1 = 0ull, a2 = 0ull, a3 = 0ull;
#pragma unroll
        for (int k = 0; k < 16; k += 2) {
            ulonglong2 x0 = sxu2[k];
            ulonglong2 x1 = sxu2[k + 1];
            a0 = ffma2(wrA[k],     x0.x, a0);
            a1 = ffma2(wrB[k],     x0.y, a1);
            a2 = ffma2(wrA[k + 1], x1.x, a2);
            a3 = ffma2(wrB[k + 1], x1.y, a3);
        }
        float2 f0 = *reinterpret_cast<float2*>(&a0);
        float2 f1 = *reinterpret_cast<float2*>(&a1);
        float2 f2 = *reinterpret_cast<float2*>(&a2);
        float2 f3 = *reinterpret_cast<float2*>(&a3);
        float s = ((f0.x + f0.y) + (f1.x + f1.y)) +
                  ((f2.x + f2.y) + (f3.x + f3.y));
        s += __shfl_down_sync(0xffffffffu, s, 16);     // fold halves
        if (half == 0) sred[t & 1][w][col] = s;

        __syncthreads();                                // ONE barrier per step

        // ---- pre-issue poll load for x_{t+1}: ONE uint4 per lane
        const uint4* p =
            reinterpret_cast<const uint4*>(&g_X[(size_t)t * RES]) + w * 32 + lane;
        uint4 A0;
        const bool more = (t < T_STEPS - 1);
        if (more) A0 = ldv_u4(p);

        // ---- finalize (warp 0, lanes 0-15): tanh update, publish x_{t+1}
        if (w == 0 && lane < NC) {
            float tot = 0.0f;
#pragma unroll
            for (int ww = 0; ww < NW; ww++) tot += sred[t & 1][ww][lane];
            float xn = omd * xold + dmp * ftanh(drv + tot);
            xold = xn;
            __stcg(&g_X[(size_t)t * RES + cbj + lane], xn);   // the "signal"
            if (more)
                drv = __ldcg(&g_drive[(size_t)(t + 1) * RES + cbj + lane]);
        }
        if (!more) break;

        // ---- single-pump check loop (consumes pre-issued load first)
        for (;;) {
            if (__all_sync(0xffffffffu, okq(A0))) break;
            A0 = ldv_u4(p);
        }
        sx4[w * 32 + lane] = *reinterpret_cast<float4*>(&A0);
        __syncwarp();
    }
}

// ---------------------------------------------------------------------------
// Kernel C: Y[t] = wout_bias + inp[t] @ wout_u + x_{t+1} @ wout_x
// ---------------------------------------------------------------------------
__global__ void readout_kernel(const float* __restrict__ inp,
                               const float* __restrict__ Wout,
                               float* __restrict__ out) {
    const int w    = threadIdx.x >> 5;
    const int lane = threadIdx.x & 31;
    const int t    = blockIdx.x * 8 + w;

    float acc[NO];
#pragma unroll
    for (int o = 0; o < NO; o++) acc[o] = 0.0f;

    const float* xrow = &g_X[(size_t)t * RES];
    for (int it = 0; it < RES / 32; it++) {
        int r = it * 32 + lane;
        float xv = xrow[r];
        const float4* wrow =
            reinterpret_cast<const float4*>(&Wout[(size_t)(1 + NF + r) * NO]);
        float4 wa = wrow[0], wb = wrow[1];
        acc[0] += xv * wa.x; acc[1] += xv * wa.y;
        acc[2] += xv * wa.z; acc[3] += xv * wa.w;
        acc[4] += xv * wb.x; acc[5] += xv * wb.y;
        acc[6] += xv * wb.z; acc[7] += xv * wb.w;
    }
#pragma unroll
    for (int o = 0; o < NO; o++) {
#pragma unroll
        for (int sft = 16; sft > 0; sft >>= 1)
            acc[o] += __shfl_down_sync(0xffffffffu, acc[o], sft);
    }
    if (lane == 0) {
#pragma unroll
        for (int o = 0; o < NO; o++) {
            float y = Wout[o];
#pragma unroll
            for (int f = 0; f < NF; f++)
                y += inp[t * NF + f] * Wout[(1 + f) * NO + o];
            out[t * NO + o] = y + acc[o];
        }
    }
}

// ---------------------------------------------------------------------------
extern "C" void kernel_launch(void* const* d_in, const int* in_sizes, int n_in,
                              void* d_out, int out_size) {
    const float* inp  = (const float*)d_in[0];   // (4096, 8)
    const float* Win  = (const float*)d_in[1];   // (9, 2048)
    const float* W    = (const float*)d_in[2];   // (2048, 2048)
    const float* Wout = (const float*)d_in[3];   // (2057, 8)
    float* out = (float*)d_out;                  // (4096, 8) fp32

    dim3 ga(RES / 256, T_STEPS);
    drive_kernel<<<ga, 256>>>(inp, Win);         // also poisons g_X
    scan_kernel<<<GRID_B, BLOCK_B>>>(W);
    readout_kernel<<<T_STEPS / 8, 256>>>(inp, Wout, out);
}